// round 2
// baseline (speedup 1.0000x reference)
#include <cuda_runtime.h>
#include <math.h>

#define NPIX0 (512*512)

// Scratch (allocation-free: __device__ globals)
__device__ unsigned char  g_labels[NPIX0];       // 256 KB
__device__ unsigned short g_mask1[256*256];      // 128 KB
__device__ unsigned short g_mask2[128*128];      // 32 KB
__device__ unsigned short g_mask3[64*64];        // 8 KB
__device__ int            g_parts[16*480];       // vec as int-bits of non-neg floats
__device__ float          g_hidden[16*240];

// ---------------------------------------------------------------------------
// Kernel A: argmax over 16 channels + copy encoded to output + build pooled
// label bitmasks (tile-local 2x2 OR pooling) + zero the parts accumulator.
// Tile: 32 wide x 8 tall pixels, grid (16, 64).
// ---------------------------------------------------------------------------
__global__ void kA(const float* __restrict__ enc, float* __restrict__ out_enc) {
    int tx = threadIdx.x, ty = threadIdx.y;
    int x = blockIdx.x * 32 + tx;
    int y = blockIdx.y * 8 + ty;
    int px = y * 512 + x;

    float best = enc[px];
    int bi = 0;
    if (out_enc) out_enc[px] = best;
#pragma unroll
    for (int c = 1; c < 16; c++) {
        float v = enc[c * NPIX0 + px];
        if (out_enc) out_enc[c * NPIX0 + px] = v;
        if (v > best) { best = v; bi = c; }
    }
    g_labels[px] = (unsigned char)bi;

    __shared__ unsigned int sh1[64];  // level1 cells in tile: 4 rows x 16 cols
    __shared__ unsigned int sh2[16];  // level2 cells in tile: 2 rows x 8 cols
    int tid = ty * 32 + tx;
    if (tid < 64) sh1[tid] = 0;
    if (tid < 16) sh2[tid] = 0;
    __syncthreads();

    atomicOr(&sh1[(ty >> 1) * 16 + (tx >> 1)], 1u << bi);
    __syncthreads();

    if (tid < 64) {
        int r = tid >> 4, c = tid & 15;
        int gy = blockIdx.y * 4 + r, gx = blockIdx.x * 16 + c;
        g_mask1[gy * 256 + gx] = (unsigned short)sh1[tid];
        atomicOr(&sh2[(r >> 1) * 8 + (c >> 1)], sh1[tid]);
    }
    __syncthreads();

    if (tid < 16) {
        int r = tid >> 3, c = tid & 7;
        g_mask2[(blockIdx.y * 2 + r) * 128 + blockIdx.x * 8 + c] =
            (unsigned short)sh2[tid];
    }
    if (tid < 4) {
        // tile = 4x1 level-3 cells (8x8 px each): OR of 2x2 level-2 cells
        unsigned m = sh2[tid * 2] | sh2[tid * 2 + 1] |
                     sh2[8 + tid * 2] | sh2[8 + tid * 2 + 1];
        g_mask3[blockIdx.y * 64 + blockIdx.x * 4 + tid] = (unsigned short)m;
    }
    // one block zeroes the global accumulator (safe: kC runs after kA, same stream)
    if (blockIdx.x == 0 && blockIdx.y == 0) {
        for (int i = tid; i < 16 * 480; i += 256) g_parts[i] = 0;
    }
}

// ---------------------------------------------------------------------------
// Kernel C: per-(level,channel,chunk) masked per-label max.
// Fast path: one LDG.128 + 4-way max vs. monotone lower-bound threshold.
// Slow path (rare): decode bitmask, shared atomicMax per set bit, refresh thr.
// smax as int: non-negative floats order-match their int bit patterns.
// ---------------------------------------------------------------------------
__global__ void __launch_bounds__(256) kC(const float* __restrict__ f0,
                                          const float* __restrict__ f1,
                                          const float* __restrict__ f2,
                                          const float* __restrict__ f3) {
    __shared__ int smax[16];
    int tid = threadIdx.x;
    if (tid < 16) smax[tid] = 0;
    __syncthreads();

    int b = blockIdx.x;
    const float* f;
    int level, base, count, col;
    if (b < 256) {            // f0: 32 ch x 8 chunks of 32768
        int ch = b >> 3; level = 0; base = (b & 7) * 32768; count = 32768;
        f = f0 + ch * NPIX0; col = ch;
    } else if (b < 384) {     // f1: 64 ch x 2 chunks of 32768
        int i = b - 256, ch = i >> 1; level = 1; base = (i & 1) * 32768; count = 32768;
        f = f1 + ch * 65536; col = 32 + ch;
    } else if (b < 512) {     // f2: 128 ch x 1 chunk
        int ch = b - 384; level = 2; base = 0; count = 16384;
        f = f2 + ch * 16384; col = 96 + ch;
    } else {                  // f3: 256 ch x 1 chunk
        int ch = b - 512; level = 3; base = 0; count = 4096;
        f = f3 + ch * 4096; col = 224 + ch;
    }

    volatile int* vs = smax;
    float thr = 0.0f;
    const float4* fv = (const float4*)(f + base);
    int n4 = count >> 2;

    for (int i = tid; i < n4; i += 256) {
        float4 v = fv[i];
        float vm = fmaxf(fmaxf(v.x, v.y), fmaxf(v.z, v.w));
        if (vm > thr) {
            float arr[4] = {v.x, v.y, v.z, v.w};
            int px0 = base + i * 4;
#pragma unroll
            for (int j = 0; j < 4; j++) {
                float vj = arr[j];
                if (vj <= thr) continue;
                int px = px0 + j;
                unsigned m;
                if (level == 0)      m = 1u << g_labels[px];
                else if (level == 1) m = g_mask1[px];
                else if (level == 2) m = g_mask2[px];
                else                 m = g_mask3[px];
                int vb = __float_as_int(vj);
                while (m) {
                    int k = __ffs(m) - 1;
                    m &= m - 1;
                    if (vb > vs[k]) atomicMax((int*)&smax[k], vb);
                }
            }
            int mn = vs[0];
#pragma unroll
            for (int k = 1; k < 16; k++) mn = min(mn, vs[k]);
            thr = __int_as_float(mn);
        }
    }
    __syncthreads();
    if (tid < 16) atomicMax(&g_parts[tid * 480 + col], smax[tid]);
}

// ---------------------------------------------------------------------------
// Kernel D1: hidden = vec @ W1 + b1   (16 x 480) @ (480 x 240)
// one thread per hidden element (3840 threads)
// ---------------------------------------------------------------------------
__global__ void kD1(const float* __restrict__ W1, const float* __restrict__ b1) {
    int idx = blockIdx.x * blockDim.x + threadIdx.x;
    if (idx >= 16 * 240) return;
    int r = idx / 240, c = idx - r * 240;
    float acc = b1[c];
    const int* vrow = &g_parts[r * 480];
#pragma unroll 4
    for (int i = 0; i < 480; i++)
        acc += __int_as_float(vrow[i]) * W1[i * 240 + c];
    g_hidden[idx] = acc;
}

// ---------------------------------------------------------------------------
// Kernel D2: bbox = sigmoid(hidden @ W2 + b2), drop label 0
// ---------------------------------------------------------------------------
__global__ void kD2(const float* __restrict__ W2, const float* __restrict__ b2,
                    float* __restrict__ out_bbox) {
    int t = threadIdx.x;
    if (t >= 64) return;
    int r = t >> 2, j = t & 3;
    float acc = b2[j];
#pragma unroll 4
    for (int i = 0; i < 240; i++)
        acc += g_hidden[r * 240 + i] * W2[i * 4 + j];
    float s = 1.0f / (1.0f + expf(-acc));
    if (r >= 1 && out_bbox) out_bbox[(r - 1) * 4 + j] = s;
}

extern "C" void kernel_launch(void* const* d_in, const int* in_sizes, int n_in,
                              void* d_out, int out_size) {
    const float* enc = (const float*)d_in[0];
    const float* f0  = (const float*)d_in[1];
    const float* f1  = (const float*)d_in[2];
    const float* f2  = (const float*)d_in[3];
    const float* f3  = (const float*)d_in[4];
    const float* W1  = (const float*)d_in[5];
    const float* b1  = (const float*)d_in[6];
    const float* W2  = (const float*)d_in[7];
    const float* b2  = (const float*)d_in[8];
    float* out = (float*)d_out;

    // Output layout: (bbox[1,15,4], encoded[1,16,512,512]) flattened in order.
    float* out_bbox = nullptr;
    float* out_enc  = nullptr;
    const int ENC_N = 16 * NPIX0;
    if (out_size >= 60 + ENC_N) { out_bbox = out; out_enc = out + 60; }
    else if (out_size >= ENC_N) { out_enc = out; }
    else                        { out_bbox = out; }

    dim3 blkA(32, 8), grdA(16, 64);
    kA<<<grdA, blkA>>>(enc, out_enc);
    kC<<<768, 256>>>(f0, f1, f2, f3);
    kD1<<<15, 256>>>(W1, b1);
    kD2<<<1, 64>>>(W2, b2, out_bbox);
}

// round 7
// speedup vs baseline: 1.7968x; 1.7968x over previous
#include <cuda_runtime.h>
#include <math.h>

#define NPIX0 (512*512)

// Scratch (allocation-free: __device__ globals)
__device__ unsigned char  g_labels[NPIX0];       // 256 KB
__device__ unsigned short g_mask1[256*256];      // 128 KB
__device__ unsigned short g_mask2[128*128];      // 32 KB
__device__ unsigned short g_mask3[64*64];        // 8 KB
__device__ int            g_parts[16*480];       // vec as int-bits of non-neg floats
__device__ float          g_hidden[16*240];

// ---------------------------------------------------------------------------
// Kernel A (vectorized float4): argmax over 16 channels + copy encoded to
// output + build pooled label bitmasks + zero parts accumulator.
// Block (32,8) threads, each thread owns 4 consecutive pixels.
// Tile: 128 wide x 8 tall. Grid (4, 64).
// ---------------------------------------------------------------------------
__global__ void kA(const float* __restrict__ enc, float* __restrict__ out_enc) {
    int tx = threadIdx.x, ty = threadIdx.y;
    int x4 = (blockIdx.x * 32 + tx) * 4;
    int y  = blockIdx.y * 8 + ty;
    int px = y * 512 + x4;
    int px4 = px >> 2;

    const float4* e4 = (const float4*)enc;
    float4*       o4 = (float4*)out_enc;

    float4 v = e4[px4];
    if (out_enc) o4[px4] = v;
    float b0 = v.x, b1v = v.y, b2v = v.z, b3 = v.w;
    int i0 = 0, i1 = 0, i2 = 0, i3 = 0;
#pragma unroll
    for (int c = 1; c < 16; c++) {
        float4 w = e4[c * (NPIX0 / 4) + px4];
        if (out_enc) o4[c * (NPIX0 / 4) + px4] = w;
        if (w.x > b0) { b0 = w.x; i0 = c; }
        if (w.y > b1v) { b1v = w.y; i1 = c; }
        if (w.z > b2v) { b2v = w.z; i2 = c; }
        if (w.w > b3) { b3 = w.w; i3 = c; }
    }
    uchar4 lab = make_uchar4((unsigned char)i0, (unsigned char)i1,
                             (unsigned char)i2, (unsigned char)i3);
    *(uchar4*)&g_labels[px] = lab;

    // Level-1 cells: 2x2 px. Tile has 4 rows x 64 cols of them.
    __shared__ unsigned int sh1[256];
    __shared__ unsigned int sh2[64];   // level-2: 2 rows x 32 cols
    __shared__ unsigned int sh3[16];   // level-3: 1 row  x 16 cols
    int tid = ty * 32 + tx;
    sh1[tid] = 0;
    if (tid < 64) sh2[tid] = 0;
    if (tid < 16) sh3[tid] = 0;
    __syncthreads();

    unsigned m0 = (1u << i0) | (1u << i1);
    unsigned m1 = (1u << i2) | (1u << i3);
    int ry = ty >> 1;
    atomicOr(&sh1[ry * 64 + tx * 2],     m0);
    atomicOr(&sh1[ry * 64 + tx * 2 + 1], m1);
    __syncthreads();

    {   // every thread owns one level-1 cell
        int r1 = tid >> 6, c1 = tid & 63;
        unsigned m = sh1[tid];
        g_mask1[(blockIdx.y * 4 + r1) * 256 + blockIdx.x * 64 + c1] =
            (unsigned short)m;
        atomicOr(&sh2[(r1 >> 1) * 32 + (c1 >> 1)], m);
    }
    __syncthreads();
    if (tid < 64) {
        int r2 = tid >> 5, c2 = tid & 31;
        unsigned m = sh2[tid];
        g_mask2[(blockIdx.y * 2 + r2) * 128 + blockIdx.x * 32 + c2] =
            (unsigned short)m;
        atomicOr(&sh3[c2 >> 1], m);
    }
    __syncthreads();
    if (tid < 16)
        g_mask3[blockIdx.y * 64 + blockIdx.x * 16 + tid] = (unsigned short)sh3[tid];

    if (blockIdx.x == 0 && blockIdx.y == 0)
        for (int i = tid; i < 16 * 480; i += 256) g_parts[i] = 0;
}

// ---------------------------------------------------------------------------
// Kernel C: per-(level,channel,chunk) masked per-label max.
// 4-way unrolled mainloop: 4 unconditional LDG.128 issue before any
// threshold branch (MLP>=4). Slow path (rare): decode bitmask, shared
// atomicMax per set bit, refresh monotone threshold.
// ---------------------------------------------------------------------------
__global__ void __launch_bounds__(256) kC(const float* __restrict__ f0,
                                          const float* __restrict__ f1,
                                          const float* __restrict__ f2,
                                          const float* __restrict__ f3) {
    __shared__ int smax[16];
    int tid = threadIdx.x;
    if (tid < 16) smax[tid] = 0;
    __syncthreads();

    int b = blockIdx.x;
    const float* f;
    int level, base, count, col;
    if (b < 256) {            // f0: 32 ch x 8 chunks of 32768
        int ch = b >> 3; level = 0; base = (b & 7) * 32768; count = 32768;
        f = f0 + ch * NPIX0; col = ch;
    } else if (b < 384) {     // f1: 64 ch x 2 chunks of 32768
        int i = b - 256, ch = i >> 1; level = 1; base = (i & 1) * 32768; count = 32768;
        f = f1 + ch * 65536; col = 32 + ch;
    } else if (b < 512) {     // f2: 128 ch x 1 chunk of 16384
        int ch = b - 384; level = 2; base = 0; count = 16384;
        f = f2 + ch * 16384; col = 96 + ch;
    } else {                  // f3: 256 ch x 1 chunk of 4096
        int ch = b - 512; level = 3; base = 0; count = 4096;
        f = f3 + ch * 4096; col = 224 + ch;
    }

    volatile int* vs = smax;
    float thr = 0.0f;
    const float4* fv = (const float4*)(f + base);
    int n4 = count >> 2;   // 8192 / 4096 / 1024 -- all divisible by 1024

#define PROC(V, I)                                                             \
    {                                                                          \
        float _vm = fmaxf(fmaxf((V).x, (V).y), fmaxf((V).z, (V).w));           \
        if (_vm > thr) {                                                       \
            float _arr[4] = {(V).x, (V).y, (V).z, (V).w};                      \
            int _px0 = base + (I) * 4;                                         \
            _Pragma("unroll")                                                  \
            for (int _j = 0; _j < 4; _j++) {                                   \
                float _vj = _arr[_j];                                          \
                if (_vj <= thr) continue;                                      \
                int _px = _px0 + _j;                                           \
                unsigned _m;                                                   \
                if (level == 0)      _m = 1u << g_labels[_px];                 \
                else if (level == 1) _m = g_mask1[_px];                        \
                else if (level == 2) _m = g_mask2[_px];                        \
                else                 _m = g_mask3[_px];                        \
                int _vb = __float_as_int(_vj);                                 \
                while (_m) {                                                   \
                    int _k = __ffs(_m) - 1;                                    \
                    _m &= _m - 1;                                              \
                    if (_vb > vs[_k]) atomicMax((int*)&smax[_k], _vb);         \
                }                                                              \
            }                                                                  \
            int _mn = vs[0];                                                   \
            _Pragma("unroll")                                                  \
            for (int _k = 1; _k < 16; _k++) _mn = min(_mn, vs[_k]);            \
            thr = __int_as_float(_mn);                                         \
        }                                                                      \
    }

    for (int i = tid; i < n4; i += 1024) {
        float4 v0 = fv[i];
        float4 v1 = fv[i + 256];
        float4 v2 = fv[i + 512];
        float4 v3 = fv[i + 768];
        PROC(v0, i)
        PROC(v1, i + 256)
        PROC(v2, i + 512)
        PROC(v3, i + 768)
    }
#undef PROC

    __syncthreads();
    if (tid < 16) atomicMax(&g_parts[tid * 480 + col], smax[tid]);
}

// ---------------------------------------------------------------------------
// Kernel D1: hidden = vec @ W1 + b1  (16x480 @ 480x240), 8-way K-split.
// 120 blocks x 256 threads; thread = (output, slice); 60 MACs each.
// ---------------------------------------------------------------------------
__global__ void __launch_bounds__(256) kD1(const float* __restrict__ W1,
                                           const float* __restrict__ b1) {
    int t = threadIdx.x;
    int c_local = t & 31, slice = t >> 5;        // 8 slices of 60
    int out = blockIdx.x * 32 + c_local;         // 0..3839
    int r = out / 240, c = out - r * 240;
    const float* w = W1 + slice * 60 * 240 + c;
    const int* vp = g_parts + r * 480 + slice * 60;
    float acc = 0.0f;
#pragma unroll 12
    for (int ii = 0; ii < 60; ii++)
        acc += __int_as_float(vp[ii]) * w[ii * 240];

    __shared__ float s[256];
    s[t] = acc;
    __syncthreads();
    if (slice == 0) {
        float a = s[c_local];
#pragma unroll
        for (int k = 1; k < 8; k++) a += s[k * 32 + c_local];
        g_hidden[out] = a + b1[c];
    }
}

// ---------------------------------------------------------------------------
// Kernel D2: bbox = sigmoid(hidden @ W2 + b2), drop label 0. 4-way K-split.
// 1 block x 256 threads; thread = (output, slice); 60 MACs each.
// ---------------------------------------------------------------------------
__global__ void kD2(const float* __restrict__ W2, const float* __restrict__ b2,
                    float* __restrict__ out_bbox) {
    int t = threadIdx.x;
    int out = t >> 2, s4 = t & 3;                // 64 outputs x 4 slices
    int r = out >> 2, j = out & 3;
    const float* hp = g_hidden + r * 240 + s4 * 60;
    const float* wp = W2 + s4 * 60 * 4 + j;
    float acc = (s4 == 0) ? b2[j] : 0.0f;
#pragma unroll 12
    for (int ii = 0; ii < 60; ii++)
        acc += hp[ii] * wp[ii * 4];

    __shared__ float s[256];
    s[t] = acc;
    __syncthreads();
    if (s4 == 0) {
        float a = s[t] + s[t + 1] + s[t + 2] + s[t + 3];
        if (r >= 1 && out_bbox)
            out_bbox[(r - 1) * 4 + j] = 1.0f / (1.0f + expf(-a));
    }
}

extern "C" void kernel_launch(void* const* d_in, const int* in_sizes, int n_in,
                              void* d_out, int out_size) {
    const float* enc = (const float*)d_in[0];
    const float* f0  = (const float*)d_in[1];
    const float* f1  = (const float*)d_in[2];
    const float* f2  = (const float*)d_in[3];
    const float* f3  = (const float*)d_in[4];
    const float* W1  = (const float*)d_in[5];
    const float* b1  = (const float*)d_in[6];
    const float* W2  = (const float*)d_in[7];
    const float* b2  = (const float*)d_in[8];
    float* out = (float*)d_out;

    // Output layout: (bbox[1,15,4], encoded[1,16,512,512]) flattened in order.
    float* out_bbox = nullptr;
    float* out_enc  = nullptr;
    const int ENC_N = 16 * NPIX0;
    if (out_size >= 60 + ENC_N) { out_bbox = out; out_enc = out + 60; }
    else if (out_size >= ENC_N) { out_enc = out; }
    else                        { out_bbox = out; }

    dim3 blkA(32, 8), grdA(4, 64);
    kA<<<grdA, blkA>>>(enc, out_enc);
    kC<<<768, 256>>>(f0, f1, f2, f3);
    kD1<<<120, 256>>>(W1, b1);
    kD2<<<1, 256>>>(W2, b2, out_bbox);
}

// round 8
// speedup vs baseline: 2.0527x; 1.1424x over previous
#include <cuda_runtime.h>
#include <math.h>

#define NPIX0 (512*512)

// Scratch (allocation-free: __device__ globals)
__device__ unsigned char  g_labels[NPIX0];       // 256 KB
__device__ unsigned short g_mask1[256*256];      // 128 KB
__device__ unsigned short g_mask2[128*128];      // 32 KB
__device__ unsigned short g_mask3[64*64];        // 8 KB
__device__ int            g_parts[16*480];       // vec as int-bits of non-neg floats

// ---------------------------------------------------------------------------
// Kernel A: argmax over 16 channels (float4-vectorized) + pooled label
// bitmasks (tile-local 2x2 OR pooling) + zero parts accumulator.
// NO copy here -- the encoded copy is a memcpy node that also warms L2.
// Block (32,8); each thread owns 4 consecutive pixels. Grid (4, 64).
// ---------------------------------------------------------------------------
__global__ void kA(const float* __restrict__ enc) {
    int tx = threadIdx.x, ty = threadIdx.y;
    int x4 = (blockIdx.x * 32 + tx) * 4;
    int y  = blockIdx.y * 8 + ty;
    int px = y * 512 + x4;
    int px4 = px >> 2;

    const float4* e4 = (const float4*)enc;

    float4 v = e4[px4];
    float b0 = v.x, b1v = v.y, b2v = v.z, b3 = v.w;
    int i0 = 0, i1 = 0, i2 = 0, i3 = 0;
#pragma unroll
    for (int c = 1; c < 16; c++) {
        float4 w = e4[c * (NPIX0 / 4) + px4];
        if (w.x > b0)  { b0 = w.x;  i0 = c; }
        if (w.y > b1v) { b1v = w.y; i1 = c; }
        if (w.z > b2v) { b2v = w.z; i2 = c; }
        if (w.w > b3)  { b3 = w.w;  i3 = c; }
    }
    *(uchar4*)&g_labels[px] = make_uchar4((unsigned char)i0, (unsigned char)i1,
                                          (unsigned char)i2, (unsigned char)i3);

    // Level-1 cells: 2x2 px. Tile has 4 rows x 64 cols of them.
    __shared__ unsigned int sh1[256];
    __shared__ unsigned int sh2[64];   // level-2: 2 rows x 32 cols
    __shared__ unsigned int sh3[16];   // level-3: 1 row  x 16 cols
    int tid = ty * 32 + tx;
    sh1[tid] = 0;
    if (tid < 64) sh2[tid] = 0;
    if (tid < 16) sh3[tid] = 0;
    __syncthreads();

    unsigned m0 = (1u << i0) | (1u << i1);
    unsigned m1 = (1u << i2) | (1u << i3);
    int ry = ty >> 1;
    atomicOr(&sh1[ry * 64 + tx * 2],     m0);
    atomicOr(&sh1[ry * 64 + tx * 2 + 1], m1);
    __syncthreads();

    {   // every thread owns one level-1 cell
        int r1 = tid >> 6, c1 = tid & 63;
        unsigned m = sh1[tid];
        g_mask1[(blockIdx.y * 4 + r1) * 256 + blockIdx.x * 64 + c1] =
            (unsigned short)m;
        atomicOr(&sh2[(r1 >> 1) * 32 + (c1 >> 1)], m);
    }
    __syncthreads();
    if (tid < 64) {
        int r2 = tid >> 5, c2 = tid & 31;
        unsigned m = sh2[tid];
        g_mask2[(blockIdx.y * 2 + r2) * 128 + blockIdx.x * 32 + c2] =
            (unsigned short)m;
        atomicOr(&sh3[c2 >> 1], m);
    }
    __syncthreads();
    if (tid < 16)
        g_mask3[blockIdx.y * 64 + blockIdx.x * 16 + tid] = (unsigned short)sh3[tid];

    if (blockIdx.x == 0 && blockIdx.y == 0)
        for (int i = tid; i < 16 * 480; i += 256) g_parts[i] = 0;
}

// ---------------------------------------------------------------------------
// Kernel C: masked per-label max, UNIFORM 4096-element chunks (3840 blocks).
// Each thread: exactly 4 upfront LDG.128 (MLP=4), then threshold-filtered
// processing. Slow path (rare): decode bitmask, shared atomicMax per set
// bit, refresh monotone lower-bound threshold.
// Block map: f0 2048 (32ch x 64), f1 1024 (64 x 16), f2 512 (128 x 4),
//            f3 256 (256 x 1).
// ---------------------------------------------------------------------------
__global__ void __launch_bounds__(256) kC(const float* __restrict__ f0,
                                          const float* __restrict__ f1,
                                          const float* __restrict__ f2,
                                          const float* __restrict__ f3) {
    __shared__ int smax[16];
    int tid = threadIdx.x;
    if (tid < 16) smax[tid] = 0;
    __syncthreads();

    int b = blockIdx.x;
    const float* f;
    int level, base, col;
    if (b < 2048) {            // f0
        int ch = b >> 6; level = 0; base = (b & 63) * 4096;
        f = f0 + ch * NPIX0; col = ch;
    } else if (b < 3072) {     // f1
        int i = b - 2048; int ch = i >> 4; level = 1; base = (i & 15) * 4096;
        f = f1 + ch * 65536; col = 32 + ch;
    } else if (b < 3584) {     // f2
        int i = b - 3072; int ch = i >> 2; level = 2; base = (i & 3) * 4096;
        f = f2 + ch * 16384; col = 96 + ch;
    } else {                   // f3
        int ch = b - 3584; level = 3; base = 0;
        f = f3 + ch * 4096; col = 224 + ch;
    }

    volatile int* vs = smax;
    float thr = 0.0f;
    const float4* fv = (const float4*)(f + base);

#define PROC(V, I)                                                             \
    {                                                                          \
        float _vm = fmaxf(fmaxf((V).x, (V).y), fmaxf((V).z, (V).w));           \
        if (_vm > thr) {                                                       \
            float _arr[4] = {(V).x, (V).y, (V).z, (V).w};                      \
            int _px0 = base + (I) * 4;                                         \
            _Pragma("unroll")                                                  \
            for (int _j = 0; _j < 4; _j++) {                                   \
                float _vj = _arr[_j];                                          \
                if (_vj <= thr) continue;                                      \
                int _px = _px0 + _j;                                           \
                unsigned _m;                                                   \
                if (level == 0)      _m = 1u << g_labels[_px];                 \
                else if (level == 1) _m = g_mask1[_px];                        \
                else if (level == 2) _m = g_mask2[_px];                        \
                else                 _m = g_mask3[_px];                        \
                int _vb = __float_as_int(_vj);                                 \
                while (_m) {                                                   \
                    int _k = __ffs(_m) - 1;                                    \
                    _m &= _m - 1;                                              \
                    if (_vb > vs[_k]) atomicMax((int*)&smax[_k], _vb);         \
                }                                                              \
            }                                                                  \
            int _mn = vs[0];                                                   \
            _Pragma("unroll")                                                  \
            for (int _k = 1; _k < 16; _k++) _mn = min(_mn, vs[_k]);            \
            thr = __int_as_float(_mn);                                         \
        }                                                                      \
    }

    // 4096 elems = 1024 float4; 256 threads -> 4 float4 each, all upfront.
    float4 v0 = fv[tid];
    float4 v1 = fv[tid + 256];
    float4 v2 = fv[tid + 512];
    float4 v3 = fv[tid + 768];
    PROC(v0, tid)
    PROC(v1, tid + 256)
    PROC(v2, tid + 512)
    PROC(v3, tid + 768)
#undef PROC

    __syncthreads();
    if (tid < 16) atomicMax(&g_parts[tid * 480 + col], smax[tid]);
}

// ---------------------------------------------------------------------------
// Kernel M: fused MLP. 16 independent blocks (one per label row) x 512 thr.
// Layer1: 240 outputs, 2-way K-split (240 MACs each), W1 reads coalesced.
// Layer2: 4 warp-reductions over the 240 hidden values, sigmoid, store.
// ---------------------------------------------------------------------------
__global__ void __launch_bounds__(512) kM(const float* __restrict__ W1,
                                          const float* __restrict__ b1,
                                          const float* __restrict__ W2,
                                          const float* __restrict__ b2,
                                          float* __restrict__ out_bbox) {
    __shared__ float sv[480];
    __shared__ float sp[480];     // layer1 partials (2 slices x 240)
    __shared__ float sh[240];     // hidden
    int t = threadIdx.x;
    int r = blockIdx.x;

    if (t < 480) sv[t] = __int_as_float(((const int*)g_parts)[r * 480 + t]);
    __syncthreads();

    if (t < 480) {
        int c = t % 240, slice = t / 240;
        const float* w = W1 + (slice * 240) * 240 + c;
        const float* vp = sv + slice * 240;
        float acc = 0.0f;
#pragma unroll 16
        for (int i = 0; i < 240; i++)
            acc += vp[i] * w[i * 240];
        sp[t] = acc;
    }
    __syncthreads();
    if (t < 240) sh[t] = sp[t] + sp[240 + t] + b1[t];
    __syncthreads();

    if (t < 128) {
        int j = t >> 5, lane = t & 31;
        float acc = 0.0f;
        for (int k = lane; k < 240; k += 32)
            acc += sh[k] * W2[k * 4 + j];
#pragma unroll
        for (int o = 16; o > 0; o >>= 1)
            acc += __shfl_down_sync(0xFFFFFFFFu, acc, o);
        if (lane == 0 && r >= 1 && out_bbox)
            out_bbox[(r - 1) * 4 + j] = 1.0f / (1.0f + expf(-(acc + b2[j])));
    }
}

extern "C" void kernel_launch(void* const* d_in, const int* in_sizes, int n_in,
                              void* d_out, int out_size) {
    const float* enc = (const float*)d_in[0];
    const float* f0  = (const float*)d_in[1];
    const float* f1  = (const float*)d_in[2];
    const float* f2  = (const float*)d_in[3];
    const float* f3  = (const float*)d_in[4];
    const float* W1  = (const float*)d_in[5];
    const float* b1  = (const float*)d_in[6];
    const float* W2  = (const float*)d_in[7];
    const float* b2  = (const float*)d_in[8];
    float* out = (float*)d_out;

    // Output layout: (bbox[1,15,4], encoded[1,16,512,512]) flattened in order.
    float* out_bbox = nullptr;
    float* out_enc  = nullptr;
    const int ENC_N = 16 * NPIX0;
    if (out_size >= 60 + ENC_N) { out_bbox = out; out_enc = out + 60; }
    else if (out_size >= ENC_N) { out_enc = out; }
    else                        { out_bbox = out; }

    // Copy-engine copy first: full-BW copy AND warms L2 with `encoded`
    // so kA's argmax reads hit L2.
    if (out_enc)
        cudaMemcpyAsync(out_enc, enc, (size_t)ENC_N * sizeof(float),
                        cudaMemcpyDeviceToDevice);

    dim3 blkA(32, 8), grdA(4, 64);
    kA<<<grdA, blkA>>>(enc);
    kC<<<3840, 256>>>(f0, f1, f2, f3);
    kM<<<16, 512>>>(W1, b1, W2, b2, out_bbox);
}

// round 10
// speedup vs baseline: 2.7000x; 1.3154x over previous
#include <cuda_runtime.h>
#include <math.h>

#define NPIX0 (512*512)

// Scratch (allocation-free: __device__ globals)
__device__ unsigned char  g_labels[NPIX0];       // 256 KB
__device__ unsigned short g_mask1[256*256];      // 128 KB
__device__ unsigned short g_mask2[128*128];      // 32 KB
__device__ unsigned short g_mask3[64*64];        // 8 KB
__device__ int            g_parts[16*480];       // vec as int-bits of non-neg floats

// ---------------------------------------------------------------------------
// Kernel A: argmax over 16 channels + fused copy of encoded to output +
// pooled label bitmasks (tile-local 2x2 OR pooling) + zero parts.
// Block (32,8); each thread owns 2 consecutive pixels (float2).
// Tile: 64 wide x 8 tall. Grid (8, 64) = 512 blocks (~28 warps/SM).
// ---------------------------------------------------------------------------
__global__ void kA(const float* __restrict__ enc, float* __restrict__ out_enc) {
    int tx = threadIdx.x, ty = threadIdx.y;
    int x2 = (blockIdx.x * 32 + tx) * 2;
    int y  = blockIdx.y * 8 + ty;
    int px = y * 512 + x2;
    int p2 = px >> 1;

    const float2* e2 = (const float2*)enc;
    float2*       o2 = (float2*)out_enc;

    float2 v = e2[p2];
    if (o2) o2[p2] = v;
    float b0 = v.x, b1v = v.y;
    int i0 = 0, i1 = 0;
#pragma unroll
    for (int c = 1; c < 16; c++) {
        float2 w = e2[c * (NPIX0 / 2) + p2];
        if (o2) o2[c * (NPIX0 / 2) + p2] = w;
        if (w.x > b0)  { b0 = w.x;  i0 = c; }
        if (w.y > b1v) { b1v = w.y; i1 = c; }
    }
    *(uchar2*)&g_labels[px] = make_uchar2((unsigned char)i0, (unsigned char)i1);

    // Level-1 cells (2x2 px): tile has 4 rows x 32 cols.
    __shared__ unsigned int sh1[128];
    __shared__ unsigned int sh2[32];   // level-2: 2 rows x 16 cols
    __shared__ unsigned int sh3[8];    // level-3: 1 row  x 8 cols
    int tid = ty * 32 + tx;
    if (tid < 128) sh1[tid] = 0;
    if (tid < 32)  sh2[tid] = 0;
    if (tid < 8)   sh3[tid] = 0;
    __syncthreads();

    atomicOr(&sh1[(ty >> 1) * 32 + tx], (1u << i0) | (1u << i1));
    __syncthreads();

    if (tid < 128) {
        int r1 = tid >> 5, c1 = tid & 31;
        unsigned m = sh1[tid];
        g_mask1[(blockIdx.y * 4 + r1) * 256 + blockIdx.x * 32 + c1] =
            (unsigned short)m;
        atomicOr(&sh2[(r1 >> 1) * 16 + (c1 >> 1)], m);
    }
    __syncthreads();
    if (tid < 32) {
        int r2 = tid >> 4, c2 = tid & 15;
        unsigned m = sh2[tid];
        g_mask2[(blockIdx.y * 2 + r2) * 128 + blockIdx.x * 16 + c2] =
            (unsigned short)m;
        atomicOr(&sh3[c2 >> 1], m);
    }
    __syncthreads();
    if (tid < 8)
        g_mask3[blockIdx.y * 64 + blockIdx.x * 8 + tid] = (unsigned short)sh3[tid];

    if (blockIdx.x == 0 && blockIdx.y == 0)
        for (int i = tid; i < 16 * 480; i += 256) g_parts[i] = 0;
}

// ---------------------------------------------------------------------------
// Kernel C: masked per-label max, 16K-element chunks (1152 blocks) with
// TWO-PHASE warmup: after the first 4-float4 batch, sync and refresh the
// monotone threshold from the fully-populated smax, then process the rest
// with a converged threshold (slow path becomes record-rate rare).
// Block map: f0 512 (32ch x 16), f1 256 (64 x 4), f2 128 (128 x 1),
//            f3 256 (256 x 1, 4K elems).
// ---------------------------------------------------------------------------
__global__ void __launch_bounds__(256) kC(const float* __restrict__ f0,
                                          const float* __restrict__ f1,
                                          const float* __restrict__ f2,
                                          const float* __restrict__ f3) {
    __shared__ int smax[16];
    int tid = threadIdx.x;
    if (tid < 16) smax[tid] = 0;
    __syncthreads();

    int b = blockIdx.x;
    const float* f;
    int level, base, col, n4;
    if (b < 512) {             // f0: 32 ch x 16 chunks of 16384
        int ch = b >> 4; level = 0; base = (b & 15) * 16384;
        f = f0 + ch * NPIX0; col = ch; n4 = 4096;
    } else if (b < 768) {      // f1: 64 ch x 4 chunks of 16384
        int i = b - 512; int ch = i >> 2; level = 1; base = (i & 3) * 16384;
        f = f1 + ch * 65536; col = 32 + ch; n4 = 4096;
    } else if (b < 896) {      // f2: 128 ch x 1 chunk of 16384
        int ch = b - 768; level = 2; base = 0;
        f = f2 + ch * 16384; col = 96 + ch; n4 = 4096;
    } else {                   // f3: 256 ch x 1 chunk of 4096
        int ch = b - 896; level = 3; base = 0;
        f = f3 + ch * 4096; col = 224 + ch; n4 = 1024;
    }

    volatile int* vs = smax;
    float thr = 0.0f;
    const float4* fv = (const float4*)(f + base);

#define PROC(V, I)                                                             \
    {                                                                          \
        float _vm = fmaxf(fmaxf((V).x, (V).y), fmaxf((V).z, (V).w));           \
        if (_vm > thr) {                                                       \
            float _arr[4] = {(V).x, (V).y, (V).z, (V).w};                      \
            int _px0 = base + (I) * 4;                                         \
            _Pragma("unroll")                                                  \
            for (int _j = 0; _j < 4; _j++) {                                   \
                float _vj = _arr[_j];                                          \
                if (_vj <= thr) continue;                                      \
                int _px = _px0 + _j;                                           \
                unsigned _m;                                                   \
                if (level == 0)      _m = 1u << g_labels[_px];                 \
                else if (level == 1) _m = g_mask1[_px];                        \
                else if (level == 2) _m = g_mask2[_px];                        \
                else                 _m = g_mask3[_px];                        \
                int _vb = __float_as_int(_vj);                                 \
                while (_m) {                                                   \
                    int _k = __ffs(_m) - 1;                                    \
                    _m &= _m - 1;                                              \
                    if (_vb > vs[_k]) atomicMax((int*)&smax[_k], _vb);         \
                }                                                              \
            }                                                                  \
            int _mn = vs[0];                                                   \
            _Pragma("unroll")                                                  \
            for (int _k = 1; _k < 16; _k++) _mn = min(_mn, vs[_k]);            \
            thr = __int_as_float(_mn);                                         \
        }                                                                      \
    }

    // Phase A: first 1024 float4s (4 per thread) -- warmup.
    {
        float4 v0 = fv[tid];
        float4 v1 = fv[tid + 256];
        float4 v2 = fv[tid + 512];
        float4 v3 = fv[tid + 768];
        PROC(v0, tid)
        PROC(v1, tid + 256)
        PROC(v2, tid + 512)
        PROC(v3, tid + 768)
    }
    __syncthreads();
    {   // refresh threshold for ALL threads from the converged smax
        int mn = vs[0];
#pragma unroll
        for (int k = 1; k < 16; k++) mn = min(mn, vs[k]);
        thr = __int_as_float(mn);
    }

    // Phase B: remaining batches with a good threshold.
    for (int off = 1024; off < n4; off += 1024) {
        float4 v0 = fv[off + tid];
        float4 v1 = fv[off + tid + 256];
        float4 v2 = fv[off + tid + 512];
        float4 v3 = fv[off + tid + 768];
        PROC(v0, off + tid)
        PROC(v1, off + tid + 256)
        PROC(v2, off + tid + 512)
        PROC(v3, off + tid + 768)
    }
#undef PROC

    __syncthreads();
    if (tid < 16) atomicMax(&g_parts[tid * 480 + col], smax[tid]);
}

// ---------------------------------------------------------------------------
// Kernel M: fused MLP. 16 independent blocks (one per label row) x 512 thr.
// Layer1: 240 outputs, 2-way K-split (240 MACs each), W1 reads coalesced.
// Layer2: 4 warp-reductions over the 240 hidden values, sigmoid, store.
// ---------------------------------------------------------------------------
__global__ void __launch_bounds__(512) kM(const float* __restrict__ W1,
                                          const float* __restrict__ b1,
                                          const float* __restrict__ W2,
                                          const float* __restrict__ b2,
                                          float* __restrict__ out_bbox) {
    __shared__ float sv[480];
    __shared__ float sp[480];     // layer1 partials (2 slices x 240)
    __shared__ float sh[240];     // hidden
    int t = threadIdx.x;
    int r = blockIdx.x;

    if (t < 480) sv[t] = __int_as_float(((const int*)g_parts)[r * 480 + t]);
    __syncthreads();

    if (t < 480) {
        int c = t % 240, slice = t / 240;
        const float* w = W1 + (slice * 240) * 240 + c;
        const float* vp = sv + slice * 240;
        float acc = 0.0f;
#pragma unroll 16
        for (int i = 0; i < 240; i++)
            acc += vp[i] * w[i * 240];
        sp[t] = acc;
    }
    __syncthreads();
    if (t < 240) sh[t] = sp[t] + sp[240 + t] + b1[t];
    __syncthreads();

    if (t < 128) {
        int j = t >> 5, lane = t & 31;
        float acc = 0.0f;
        for (int k = lane; k < 240; k += 32)
            acc += sh[k] * W2[k * 4 + j];
#pragma unroll
        for (int o = 16; o > 0; o >>= 1)
            acc += __shfl_down_sync(0xFFFFFFFFu, acc, o);
        if (lane == 0 && r >= 1 && out_bbox)
            out_bbox[(r - 1) * 4 + j] = 1.0f / (1.0f + expf(-(acc + b2[j])));
    }
}

extern "C" void kernel_launch(void* const* d_in, const int* in_sizes, int n_in,
                              void* d_out, int out_size) {
    const float* enc = (const float*)d_in[0];
    const float* f0  = (const float*)d_in[1];
    const float* f1  = (const float*)d_in[2];
    const float* f2  = (const float*)d_in[3];
    const float* f3  = (const float*)d_in[4];
    const float* W1  = (const float*)d_in[5];
    const float* b1  = (const float*)d_in[6];
    const float* W2  = (const float*)d_in[7];
    const float* b2  = (const float*)d_in[8];
    float* out = (float*)d_out;

    // Output layout: (bbox[1,15,4], encoded[1,16,512,512]) flattened in order.
    float* out_bbox = nullptr;
    float* out_enc  = nullptr;
    const int ENC_N = 16 * NPIX0;
    if (out_size >= 60 + ENC_N) { out_bbox = out; out_enc = out + 60; }
    else if (out_size >= ENC_N) { out_enc = out; }
    else                        { out_bbox = out; }

    dim3 blkA(32, 8), grdA(8, 64);
    kA<<<grdA, blkA>>>(enc, out_enc);
    kC<<<1152, 256>>>(f0, f1, f2, f3);
    kM<<<16, 512>>>(W1, b1, W2, b2, out_bbox);
}